// round 1
// baseline (speedup 1.0000x reference)
#include <cuda_runtime.h>
#include <cstdint>

#define NNODES 100000
#define EEDGES 1600000
#define FF 32
#define HH 128
#define LLAYERS 4
#define GG 64
#define H3 384

// ---------------- scratch (device globals; no allocation) ----------------
__device__ float g_h[(size_t)NNODES * HH];      // node state
__device__ float g_m[(size_t)NNODES * HH];      // conv output
__device__ float g_agg[(size_t)NNODES * HH];    // scatter target
__device__ float g_gi[(size_t)NNODES * H3];     // agg @ w_ih^T
__device__ float g_gh[(size_t)NNODES * H3];     // h   @ w_hh^T
__device__ float g_outv[NNODES];                // uncorrected head output
__device__ float g_gsum[GG];
__device__ float g_gcnt[GG];
__device__ int   g_src[EEDGES];
__device__ int   g_dst[EEDGES];
__device__ int   g_batch[NNODES];
__device__ int   g_edge_i32;                    // 1 => edge_index is int32
__device__ int   g_batch_i32;                   // 1 => batch is int32

// ---------------- f32x2 helpers ----------------
__device__ __forceinline__ void fma2(unsigned long long& d, unsigned long long a,
                                     unsigned long long b) {
    asm("fma.rn.f32x2 %0, %1, %2, %3;" : "=l"(d) : "l"(a), "l"(b), "l"(d));
}
__device__ __forceinline__ unsigned long long pack_dup(float x) {
    unsigned long long r;
    asm("mov.b64 %0, {%1, %1};" : "=l"(r) : "f"(x));
    return r;
}
__device__ __forceinline__ float2 unpack2(unsigned long long v) {
    float2 r;
    asm("mov.b64 {%0, %1}, %2;" : "=f"(r.x), "=f"(r.y) : "l"(v));
    return r;
}
__device__ __forceinline__ float sigf(float x) { return 1.f / (1.f + __expf(-x)); }
__device__ __forceinline__ float tanhfast(float x) {
    float ax = fabsf(x);
    float e = __expf(-2.f * ax);
    float t = (1.f - e) / (1.f + e);
    return copysignf(t, x);
}

// ---------------- small utility kernels ----------------
__global__ void zero_small_kernel() {
    int t = threadIdx.x;
    if (t < GG) { g_gsum[t] = 0.f; g_gcnt[t] = 0.f; }
    if (t == 127) { g_edge_i32 = 0; g_batch_i32 = 0; }
}

// Scan odd 32-bit words of a buffer interpreted as u32[nwords]. For genuine
// int64 data (values < 2^31, nonneg) all odd words are 0. Any nonzero => int32.
__global__ void detect_kernel(const unsigned int* __restrict__ p, long long nwords, int which) {
    long long i = 1 + 2LL * (blockIdx.x * (long long)blockDim.x + threadIdx.x);
    long long stride = 2LL * gridDim.x * blockDim.x;
    int found = 0;
    for (; i < nwords; i += stride)
        if (p[i]) { found = 1; break; }
    if (found) { if (which == 0) g_edge_i32 = 1; else g_batch_i32 = 1; }
}

__global__ void convert_edges_kernel(const void* __restrict__ e) {
    int i = blockIdx.x * 256 + threadIdx.x;
    if (i >= EEDGES) return;
    if (g_edge_i32) {
        const int* p = (const int*)e;
        g_src[i] = p[i];
        g_dst[i] = p[EEDGES + i];
    } else {
        const long long* p = (const long long*)e;
        g_src[i] = (int)p[i];
        g_dst[i] = (int)p[EEDGES + i];
    }
}

__global__ void convert_batch_kernel(const void* __restrict__ b) {
    int i = blockIdx.x * 256 + threadIdx.x;
    if (i >= NNODES) return;
    if (g_batch_i32) g_batch[i] = ((const int*)b)[i];
    else             g_batch[i] = (int)((const long long*)b)[i];
}

__global__ void zero_agg_kernel() {
    size_t i = ((size_t)blockIdx.x * 256 + threadIdx.x) * 4;
    *(float4*)(g_agg + i) = make_float4(0.f, 0.f, 0.f, 0.f);
}

// ---------------- embed: h = x_embed = sigmoid(x @ W0^T) ----------------
// Tile 128 nodes x 128 outputs, K=32. Writes both g_h and d_out x_embed slab.
__global__ void embed_kernel(const float* __restrict__ x, const float* __restrict__ W0,
                             float* __restrict__ out_emb) {
    __shared__ float xT[FF * 128];   // xT[k*128 + i]
    __shared__ float wT[FF * 128];   // wT[k*128 + j] = W0[j*32 + k]
    int m0 = blockIdx.x * 128;
    int tid = threadIdx.x;
    {
        int i = tid >> 1;
        int q0 = (tid & 1) * 4;
        bool ok = (m0 + i) < NNODES;
        const float4* xr = (const float4*)(x + (size_t)(m0 + i) * FF);
        const float4* wr = (const float4*)(W0 + (size_t)i * FF);
#pragma unroll
        for (int q = 0; q < 4; q++) {
            float4 v = ok ? xr[q0 + q] : make_float4(0.f, 0.f, 0.f, 0.f);
            int k = (q0 + q) * 4;
            xT[(k + 0) * 128 + i] = v.x; xT[(k + 1) * 128 + i] = v.y;
            xT[(k + 2) * 128 + i] = v.z; xT[(k + 3) * 128 + i] = v.w;
        }
#pragma unroll
        for (int q = 0; q < 4; q++) {
            float4 v = wr[q0 + q];
            int k = (q0 + q) * 4;
            wT[(k + 0) * 128 + i] = v.x; wT[(k + 1) * 128 + i] = v.y;
            wT[(k + 2) * 128 + i] = v.z; wT[(k + 3) * 128 + i] = v.w;
        }
    }
    __syncthreads();
    int tx = tid & 15, ty = tid >> 4;
    unsigned long long acc[8][4];
#pragma unroll
    for (int i = 0; i < 8; i++)
#pragma unroll
        for (int j = 0; j < 4; j++) acc[i][j] = 0ull;

    const float* aBase = xT + ty * 8;
    const float* bBase = wT + tx * 8;
#pragma unroll 4
    for (int k = 0; k < FF; k++) {
        float4 a0 = *(const float4*)(aBase + k * 128);
        float4 a1 = *(const float4*)(aBase + k * 128 + 4);
        const unsigned long long* bp = (const unsigned long long*)(bBase + k * 128);
        unsigned long long b0 = bp[0], b1 = bp[1], b2 = bp[2], b3 = bp[3];
        float av[8] = {a0.x, a0.y, a0.z, a0.w, a1.x, a1.y, a1.z, a1.w};
#pragma unroll
        for (int i = 0; i < 8; i++) {
            unsigned long long a2 = pack_dup(av[i]);
            fma2(acc[i][0], a2, b0); fma2(acc[i][1], a2, b1);
            fma2(acc[i][2], a2, b2); fma2(acc[i][3], a2, b3);
        }
    }
#pragma unroll
    for (int i = 0; i < 8; i++) {
        int row = m0 + ty * 8 + i;
        if (row < NNODES) {
            float2 v0 = unpack2(acc[i][0]), v1 = unpack2(acc[i][1]);
            float2 v2 = unpack2(acc[i][2]), v3 = unpack2(acc[i][3]);
            float4 o0 = make_float4(sigf(v0.x), sigf(v0.y), sigf(v1.x), sigf(v1.y));
            float4 o1 = make_float4(sigf(v2.x), sigf(v2.y), sigf(v3.x), sigf(v3.y));
            size_t off = (size_t)row * HH + tx * 8;
            *(float4*)(g_h + off) = o0;     *(float4*)(g_h + off + 4) = o1;
            *(float4*)(out_emb + off) = o0; *(float4*)(out_emb + off + 4) = o1;
        }
    }
}

// ---------------- generic K=128 GEMM: C[M,NC] = A[M,128] @ B ----------------
// transB=0: C[m,j] = sum_k A[m,k] * B[k*NC + j]        (conv_w layout)
// transB=1: C[m,j] = sum_k A[m,k] * B[j*128 + k]       (w_ih / w_hh layout)
// Tile 128x128, 256 threads, 8x8 microtile with packed f32x2 FMAs.
__global__ void gemm128_kernel(const float* __restrict__ A, const float* __restrict__ B,
                               float* __restrict__ C, int M, int NC, int transB) {
    extern __shared__ float sm[];
    float* aT = sm;               // aT[k*128 + i]
    float* ws = sm + 128 * 128;   // ws[k*128 + j]
    int m0 = blockIdx.x * 128;
    int j0 = blockIdx.y * 128;
    int tid = threadIdx.x;
    {   // A tile (transposed stage)
        int i = tid >> 1;
        int kq0 = (tid & 1) * 16;
        bool ok = (m0 + i) < M;
        const float4* Ar = (const float4*)(A + (size_t)(m0 + i) * 128);
#pragma unroll
        for (int q = 0; q < 16; q++) {
            int k4 = kq0 + q;
            float4 v = ok ? Ar[k4] : make_float4(0.f, 0.f, 0.f, 0.f);
            aT[(k4 * 4 + 0) * 128 + i] = v.x; aT[(k4 * 4 + 1) * 128 + i] = v.y;
            aT[(k4 * 4 + 2) * 128 + i] = v.z; aT[(k4 * 4 + 3) * 128 + i] = v.w;
        }
    }
    if (!transB) {  // B[k][j0+j], row stride NC
        int k = tid >> 1;
        int q0 = (tid & 1) * 16;
        const float4* Br = (const float4*)(B + (size_t)k * NC + j0);
        float4* wr = (float4*)(ws + k * 128);
#pragma unroll
        for (int q = 0; q < 16; q++) wr[q0 + q] = Br[q0 + q];
    } else {        // B[(j0+j)*128 + k] -> transpose stage
        int j = tid >> 1;
        int kq0 = (tid & 1) * 16;
        const float4* Br = (const float4*)(B + (size_t)(j0 + j) * 128);
#pragma unroll
        for (int q = 0; q < 16; q++) {
            int k4 = kq0 + q;
            float4 v = Br[k4];
            ws[(k4 * 4 + 0) * 128 + j] = v.x; ws[(k4 * 4 + 1) * 128 + j] = v.y;
            ws[(k4 * 4 + 2) * 128 + j] = v.z; ws[(k4 * 4 + 3) * 128 + j] = v.w;
        }
    }
    __syncthreads();

    int tx = tid & 15, ty = tid >> 4;
    unsigned long long acc[8][4];
#pragma unroll
    for (int i = 0; i < 8; i++)
#pragma unroll
        for (int j = 0; j < 4; j++) acc[i][j] = 0ull;

    const float* aBase = aT + ty * 8;
    const float* bBase = ws + tx * 8;
#pragma unroll 4
    for (int k = 0; k < 128; k++) {
        float4 a0 = *(const float4*)(aBase + k * 128);
        float4 a1 = *(const float4*)(aBase + k * 128 + 4);
        const unsigned long long* bp = (const unsigned long long*)(bBase + k * 128);
        unsigned long long b0 = bp[0], b1 = bp[1], b2 = bp[2], b3 = bp[3];
        float av[8] = {a0.x, a0.y, a0.z, a0.w, a1.x, a1.y, a1.z, a1.w};
#pragma unroll
        for (int i = 0; i < 8; i++) {
            unsigned long long a2 = pack_dup(av[i]);
            fma2(acc[i][0], a2, b0); fma2(acc[i][1], a2, b1);
            fma2(acc[i][2], a2, b2); fma2(acc[i][3], a2, b3);
        }
    }
#pragma unroll
    for (int i = 0; i < 8; i++) {
        int row = m0 + ty * 8 + i;
        if (row < M) {
            float* cp = C + (size_t)row * NC + j0 + tx * 8;
            float2 v0 = unpack2(acc[i][0]), v1 = unpack2(acc[i][1]);
            float2 v2 = unpack2(acc[i][2]), v3 = unpack2(acc[i][3]);
            *(float4*)cp       = make_float4(v0.x, v0.y, v1.x, v1.y);
            *(float4*)(cp + 4) = make_float4(v2.x, v2.y, v3.x, v3.y);
        }
    }
}

// ---------------- scatter-add: agg[dst] += m[src], warp per edge ----------------
__global__ void scatter_kernel() {
    int gw = (blockIdx.x * 256 + threadIdx.x) >> 5;
    int lane = threadIdx.x & 31;
    if (gw >= EEDGES) return;
    int s = g_src[gw], d = g_dst[gw];
    float4 v = *(const float4*)(g_m + (size_t)s * HH + lane * 4);
    float* p = g_agg + (size_t)d * HH + lane * 4;
    asm volatile("red.global.add.v4.f32 [%0], {%1, %2, %3, %4};"
                 :: "l"(p), "f"(v.x), "f"(v.y), "f"(v.z), "f"(v.w) : "memory");
}

// ---------------- GRU elementwise: h = GRU(agg, h) ----------------
__global__ void gru_kernel(const float* __restrict__ b_ih, const float* __restrict__ b_hh) {
    int t = blockIdx.x * 256 + threadIdx.x;   // exactly N*32 threads
    int n = t >> 5;
    int j = (t & 31) * 4;
    size_t gio = (size_t)n * H3 + j;
    float4 ir = *(const float4*)(g_gi + gio);
    float4 iz = *(const float4*)(g_gi + gio + 128);
    float4 in_ = *(const float4*)(g_gi + gio + 256);
    float4 hr = *(const float4*)(g_gh + gio);
    float4 hz = *(const float4*)(g_gh + gio + 128);
    float4 hn = *(const float4*)(g_gh + gio + 256);
    float4 bir = __ldg((const float4*)(b_ih + j));
    float4 biz = __ldg((const float4*)(b_ih + 128 + j));
    float4 bin = __ldg((const float4*)(b_ih + 256 + j));
    float4 bhr = __ldg((const float4*)(b_hh + j));
    float4 bhz = __ldg((const float4*)(b_hh + 128 + j));
    float4 bhn = __ldg((const float4*)(b_hh + 256 + j));
    float4 hv = *(const float4*)(g_h + (size_t)n * HH + j);

    float4 out;
#define GRU1(c)                                                            \
    {                                                                      \
        float r = sigf(ir.c + bir.c + hr.c + bhr.c);                       \
        float z = sigf(iz.c + biz.c + hz.c + bhz.c);                       \
        float ng = tanhfast(in_.c + bin.c + r * (hn.c + bhn.c));           \
        out.c = (1.f - z) * ng + z * hv.c;                                 \
    }
    GRU1(x) GRU1(y) GRU1(z) GRU1(w)
#undef GRU1
    *(float4*)(g_h + (size_t)n * HH + j) = out;
}

// ---------------- head: out = relu(h) @ lin1_w^T + b; per-graph sums ----------------
__global__ void lin_kernel(const float* __restrict__ lw, const float* __restrict__ lb,
                           float* __restrict__ out_unc) {
    int gw = (blockIdx.x * 256 + threadIdx.x) >> 5;
    int lane = threadIdx.x & 31;
    float4 a = *(const float4*)(g_h + (size_t)gw * HH + lane * 4);
    a.x = fmaxf(a.x, 0.f); a.y = fmaxf(a.y, 0.f);
    a.z = fmaxf(a.z, 0.f); a.w = fmaxf(a.w, 0.f);
    float4 w = __ldg((const float4*)lw + lane);
    float s = a.x * w.x + a.y * w.y + a.z * w.z + a.w * w.w;
#pragma unroll
    for (int o = 16; o; o >>= 1) s += __shfl_xor_sync(0xffffffffu, s, o);
    if (lane == 0) {
        float v = s + __ldg(lb);
        g_outv[gw] = v;
        out_unc[gw] = v;
        int b = g_batch[gw];
        atomicAdd(&g_gsum[b], v);
        atomicAdd(&g_gcnt[b], 1.f);
    }
}

__global__ void correct_kernel(float* __restrict__ out_corr) {
    int n = blockIdx.x * 256 + threadIdx.x;
    if (n >= NNODES) return;
    int b = g_batch[n];
    out_corr[n] = g_outv[n] - g_gsum[b] / fmaxf(g_gcnt[b], 1.f);
}

// ---------------- launcher ----------------
extern "C" void kernel_launch(void* const* d_in, const int* in_sizes, int n_in,
                              void* d_out, int out_size) {
    const float* x = (const float*)d_in[0];
    const void* edge = d_in[1];
    const void* batch = d_in[2];
    int wi = 3;
    if (in_sizes[3] == 1) wi = 4;   // skip num_graphs scalar if present
    const float* W0     = (const float*)d_in[wi + 0];
    const float* conv_w = (const float*)d_in[wi + 1];
    const float* w_ih   = (const float*)d_in[wi + 2];
    const float* b_ih   = (const float*)d_in[wi + 3];
    const float* w_hh   = (const float*)d_in[wi + 4];
    const float* b_hh   = (const float*)d_in[wi + 5];
    const float* lin1_w = (const float*)d_in[wi + 6];
    const float* lin1_b = (const float*)d_in[wi + 7];

    float* out = (float*)d_out;
    float* out_corr = out;
    float* out_emb  = out + NNODES;
    float* out_unc  = out + NNODES + (size_t)NNODES * HH;

    const int GEMM_SMEM = 2 * 128 * 128 * (int)sizeof(float);  // 128 KB
    cudaFuncSetAttribute(gemm128_kernel, cudaFuncAttributeMaxDynamicSharedMemorySize,
                         GEMM_SMEM);

    float *p_h, *p_m, *p_agg, *p_gi, *p_gh;
    cudaGetSymbolAddress((void**)&p_h, g_h);
    cudaGetSymbolAddress((void**)&p_m, g_m);
    cudaGetSymbolAddress((void**)&p_agg, g_agg);
    cudaGetSymbolAddress((void**)&p_gi, g_gi);
    cudaGetSymbolAddress((void**)&p_gh, g_gh);

    zero_small_kernel<<<1, 128>>>();
    detect_kernel<<<256, 256>>>((const unsigned int*)edge, 2LL * EEDGES, 0);
    detect_kernel<<<256, 256>>>((const unsigned int*)batch, (long long)NNODES, 1);
    convert_edges_kernel<<<(EEDGES + 255) / 256, 256>>>(edge);
    convert_batch_kernel<<<(NNODES + 255) / 256, 256>>>(batch);

    const int MT = (NNODES + 127) / 128;   // 782
    embed_kernel<<<MT, 256>>>(x, W0, out_emb);

    for (int l = 0; l < LLAYERS; l++) {
        gemm128_kernel<<<dim3(MT, 1), 256, GEMM_SMEM>>>(
            p_h, conv_w + (size_t)l * HH * HH, p_m, NNODES, HH, 0);
        zero_agg_kernel<<<NNODES * HH / (256 * 4), 256>>>();
        scatter_kernel<<<EEDGES * 32 / 256, 256>>>();
        gemm128_kernel<<<dim3(MT, 3), 256, GEMM_SMEM>>>(p_agg, w_ih, p_gi, NNODES, H3, 1);
        gemm128_kernel<<<dim3(MT, 3), 256, GEMM_SMEM>>>(p_h, w_hh, p_gh, NNODES, H3, 1);
        gru_kernel<<<NNODES * 32 / 256, 256>>>(b_ih, b_hh);
    }

    lin_kernel<<<NNODES * 32 / 256, 256>>>(lin1_w, lin1_b, out_unc);
    correct_kernel<<<(NNODES + 255) / 256, 256>>>(out_corr);
}

// round 2
// speedup vs baseline: 1.6037x; 1.6037x over previous
#include <cuda_runtime.h>
#include <cuda_bf16.h>
#include <cstdint>

#define NNODES 100000
#define EEDGES 1600000
#define FF 32
#define HH 128
#define LLAYERS 4
#define GG 64
#define H3 384

// ---------------- scratch (device globals; no allocation) ----------------
__device__ float g_h[(size_t)NNODES * HH];      // node state
__device__ float g_m[(size_t)NNODES * HH];      // conv output (message)
__device__ float g_agg[(size_t)NNODES * HH];    // scatter target (sum of h[src])
__device__ float g_gi[(size_t)NNODES * H3];     // m   @ w_ih^T
__device__ float g_gh[(size_t)NNODES * H3];     // h   @ w_hh^T
__device__ float g_outv[NNODES];                // uncorrected head output
__device__ float g_gsum[GG];
__device__ float g_gcnt[GG];
__device__ int   g_src[EEDGES];
__device__ int   g_dst[EEDGES];
__device__ int   g_batch[NNODES];
__device__ int   g_edge_i32;
__device__ int   g_batch_i32;

// bf16 split weights (hi/lo), n-major [out_col][k]
__device__ unsigned short g_cw_h[LLAYERS * HH * HH];
__device__ unsigned short g_cw_l[LLAYERS * HH * HH];
__device__ unsigned short g_ih_h[H3 * HH];
__device__ unsigned short g_ih_l[H3 * HH];
__device__ unsigned short g_hh_h[H3 * HH];
__device__ unsigned short g_hh_l[H3 * HH];

// ---------------- math helpers ----------------
__device__ __forceinline__ float sigf(float x) { return 1.f / (1.f + __expf(-x)); }
__device__ __forceinline__ float tanhfast(float x) {
    float ax = fabsf(x);
    float e = __expf(-2.f * ax);
    float t = (1.f - e) / (1.f + e);
    return copysignf(t, x);
}
__device__ __forceinline__ void fma2(unsigned long long& d, unsigned long long a,
                                     unsigned long long b) {
    asm("fma.rn.f32x2 %0, %1, %2, %3;" : "=l"(d) : "l"(a), "l"(b), "l"(d));
}
__device__ __forceinline__ unsigned long long pack_dup(float x) {
    unsigned long long r;
    asm("mov.b64 %0, {%1, %1};" : "=l"(r) : "f"(x));
    return r;
}
__device__ __forceinline__ float2 unpack2(unsigned long long v) {
    float2 r;
    asm("mov.b64 {%0, %1}, %2;" : "=f"(r.x), "=f"(r.y) : "l"(v));
    return r;
}

// split one float into bf16 hi + bf16 lo(residual)
__device__ __forceinline__ void split1(float a, unsigned short& h, unsigned short& l) {
    __nv_bfloat16 ha = __float2bfloat16_rn(a);
    float ra = a - __bfloat162float(ha);
    __nv_bfloat16 la = __float2bfloat16_rn(ra);
    h = __bfloat16_as_ushort(ha);
    l = __bfloat16_as_ushort(la);
}
__device__ __forceinline__ void split2(float a, float b, unsigned& h, unsigned& l) {
    unsigned short ha, la, hb, lb;
    split1(a, ha, la);
    split1(b, hb, lb);
    h = (unsigned)ha | ((unsigned)hb << 16);
    l = (unsigned)la | ((unsigned)lb << 16);
}

__device__ __forceinline__ void ldm4(unsigned r[4], uint32_t addr) {
    asm volatile("ldmatrix.sync.aligned.m8n8.x4.shared.b16 {%0,%1,%2,%3}, [%4];\n"
                 : "=r"(r[0]), "=r"(r[1]), "=r"(r[2]), "=r"(r[3])
                 : "r"(addr));
}
__device__ __forceinline__ void mma16816(float* c, const unsigned a[4],
                                         unsigned b0, unsigned b1) {
    asm volatile(
        "mma.sync.aligned.m16n8k16.row.col.f32.bf16.bf16.f32 "
        "{%0,%1,%2,%3}, {%4,%5,%6,%7}, {%8,%9}, {%0,%1,%2,%3};\n"
        : "+f"(c[0]), "+f"(c[1]), "+f"(c[2]), "+f"(c[3])
        : "r"(a[0]), "r"(a[1]), "r"(a[2]), "r"(a[3]), "r"(b0), "r"(b1));
}

// ---------------- small utility kernels ----------------
__global__ void zero_small_kernel() {
    int t = threadIdx.x;
    if (t < GG) { g_gsum[t] = 0.f; g_gcnt[t] = 0.f; }
    if (t == 127) { g_edge_i32 = 0; g_batch_i32 = 0; }
}

__global__ void detect_kernel(const unsigned int* __restrict__ p, long long nwords, int which) {
    long long i = 1 + 2LL * (blockIdx.x * (long long)blockDim.x + threadIdx.x);
    long long stride = 2LL * gridDim.x * blockDim.x;
    int found = 0;
    for (; i < nwords; i += stride)
        if (p[i]) { found = 1; break; }
    if (found) { if (which == 0) g_edge_i32 = 1; else g_batch_i32 = 1; }
}

__global__ void convert_edges_kernel(const void* __restrict__ e) {
    int i = blockIdx.x * 256 + threadIdx.x;
    if (i >= EEDGES) return;
    if (g_edge_i32) {
        const int* p = (const int*)e;
        g_src[i] = p[i];
        g_dst[i] = p[EEDGES + i];
    } else {
        const long long* p = (const long long*)e;
        g_src[i] = (int)p[i];
        g_dst[i] = (int)p[EEDGES + i];
    }
}

__global__ void convert_batch_kernel(const void* __restrict__ b) {
    int i = blockIdx.x * 256 + threadIdx.x;
    if (i >= NNODES) return;
    if (g_batch_i32) g_batch[i] = ((const int*)b)[i];
    else             g_batch[i] = (int)((const long long*)b)[i];
}

__global__ void zero_agg_kernel() {
    size_t i = ((size_t)blockIdx.x * 256 + threadIdx.x) * 4;
    *(float4*)(g_agg + i) = make_float4(0.f, 0.f, 0.f, 0.f);
}

// ---------------- weight split/convert kernels ----------------
// conv_w layout [l][k][j] -> store n-major [l][j][k]
__global__ void conv_w_split_kernel(const float* __restrict__ w) {
    int idx = blockIdx.x * 256 + threadIdx.x;   // L*128*128 = 65536
    if (idx >= LLAYERS * HH * HH) return;
    int l = idx >> 14;
    int rem = idx & 16383;
    int j = rem >> 7;
    int k = rem & 127;
    float v = w[(l << 14) + (k << 7) + j];
    unsigned short h, lo;
    split1(v, h, lo);
    g_cw_h[idx] = h;
    g_cw_l[idx] = lo;
}
// w_ih / w_hh layout [j][k] already n-major
__global__ void w2_split_kernel(const float* __restrict__ wih, const float* __restrict__ whh) {
    int idx = blockIdx.x * 256 + threadIdx.x;   // 384*128 = 49152
    if (idx >= H3 * HH) return;
    unsigned short h, lo;
    split1(wih[idx], h, lo);
    g_ih_h[idx] = h; g_ih_l[idx] = lo;
    split1(whh[idx], h, lo);
    g_hh_h[idx] = h; g_hh_l[idx] = lo;
}

// ---------------- embed: h = x_embed = sigmoid(x @ W0^T), K=32 (FFMA) ----------------
__global__ void embed_kernel(const float* __restrict__ x, const float* __restrict__ W0,
                             float* __restrict__ out_emb) {
    __shared__ float xT[FF * 128];
    __shared__ float wT[FF * 128];
    int m0 = blockIdx.x * 128;
    int tid = threadIdx.x;
    {
        int i = tid >> 1;
        int q0 = (tid & 1) * 4;
        bool ok = (m0 + i) < NNODES;
        const float4* xr = (const float4*)(x + (size_t)(m0 + i) * FF);
        const float4* wr = (const float4*)(W0 + (size_t)i * FF);
#pragma unroll
        for (int q = 0; q < 4; q++) {
            float4 v = ok ? xr[q0 + q] : make_float4(0.f, 0.f, 0.f, 0.f);
            int k = (q0 + q) * 4;
            xT[(k + 0) * 128 + i] = v.x; xT[(k + 1) * 128 + i] = v.y;
            xT[(k + 2) * 128 + i] = v.z; xT[(k + 3) * 128 + i] = v.w;
        }
#pragma unroll
        for (int q = 0; q < 4; q++) {
            float4 v = wr[q0 + q];
            int k = (q0 + q) * 4;
            wT[(k + 0) * 128 + i] = v.x; wT[(k + 1) * 128 + i] = v.y;
            wT[(k + 2) * 128 + i] = v.z; wT[(k + 3) * 128 + i] = v.w;
        }
    }
    __syncthreads();
    int tx = tid & 15, ty = tid >> 4;
    unsigned long long acc[8][4];
#pragma unroll
    for (int i = 0; i < 8; i++)
#pragma unroll
        for (int j = 0; j < 4; j++) acc[i][j] = 0ull;

    const float* aBase = xT + ty * 8;
    const float* bBase = wT + tx * 8;
#pragma unroll 4
    for (int k = 0; k < FF; k++) {
        float4 a0 = *(const float4*)(aBase + k * 128);
        float4 a1 = *(const float4*)(aBase + k * 128 + 4);
        const unsigned long long* bp = (const unsigned long long*)(bBase + k * 128);
        unsigned long long b0 = bp[0], b1 = bp[1], b2 = bp[2], b3 = bp[3];
        float av[8] = {a0.x, a0.y, a0.z, a0.w, a1.x, a1.y, a1.z, a1.w};
#pragma unroll
        for (int i = 0; i < 8; i++) {
            unsigned long long a2 = pack_dup(av[i]);
            fma2(acc[i][0], a2, b0); fma2(acc[i][1], a2, b1);
            fma2(acc[i][2], a2, b2); fma2(acc[i][3], a2, b3);
        }
    }
#pragma unroll
    for (int i = 0; i < 8; i++) {
        int row = m0 + ty * 8 + i;
        if (row < NNODES) {
            float2 v0 = unpack2(acc[i][0]), v1 = unpack2(acc[i][1]);
            float2 v2 = unpack2(acc[i][2]), v3 = unpack2(acc[i][3]);
            float4 o0 = make_float4(sigf(v0.x), sigf(v0.y), sigf(v1.x), sigf(v1.y));
            float4 o1 = make_float4(sigf(v2.x), sigf(v2.y), sigf(v3.x), sigf(v3.y));
            size_t off = (size_t)row * HH + tx * 8;
            *(float4*)(g_h + off) = o0;     *(float4*)(g_h + off + 4) = o1;
            *(float4*)(out_emb + off) = o0; *(float4*)(out_emb + off + 4) = o1;
        }
    }
}

// ---------------- tensor-core GEMM (bf16 split-3): C[M,*] tile 128x128 ----------------
// A: fp32 [M][128] row-major (converted+split on the fly)
// B: bf16 hi/lo, n-major [NC][128]
// C[m, j0+j] = sum_k A[m,k] * B[j0+j, k]
#define SAW2 72                                 // padded row stride (bf16 elems), K-chunk=64
#define MMA_SMEM (4 * 128 * SAW2 * 2)           // 73728 B

__global__ __launch_bounds__(256, 2)
void mma_gemm_kernel(const float* __restrict__ A,
                     const unsigned short* __restrict__ Bh,
                     const unsigned short* __restrict__ Bl,
                     float* __restrict__ C, int M, int ldc) {
    extern __shared__ unsigned short smx[];
    unsigned short* sAh = smx;
    unsigned short* sAl = sAh + 128 * SAW2;
    unsigned short* sBh = sAl + 128 * SAW2;
    unsigned short* sBl = sBh + 128 * SAW2;

    const int tid = threadIdx.x;
    const int m0 = blockIdx.x * 128;
    const int j0 = blockIdx.y * 128;
    const int lane = tid & 31, wid = tid >> 5;
    const int wm = wid >> 2, wn = wid & 3;   // 2 x 4 warp grid: 64 rows x 32 cols each

    float acc[4][4][4];
#pragma unroll
    for (int a = 0; a < 4; a++)
#pragma unroll
        for (int b = 0; b < 4; b++)
#pragma unroll
            for (int c = 0; c < 4; c++) acc[a][b][c] = 0.f;

    uint32_t sbase = (uint32_t)__cvta_generic_to_shared(smx);
    const uint32_t oAh = 0;
    const uint32_t oAl = 128 * SAW2 * 2;
    const uint32_t oBh = 2 * 128 * SAW2 * 2;
    const uint32_t oBl = 3 * 128 * SAW2 * 2;

    const int ai = tid >> 1;                      // row within tile (0..127)
    const int half = tid & 1;
    const bool aok = (m0 + ai) < M;
    const float4* Arow = (const float4*)(A + (size_t)(m0 + ai) * 128);
    const uint4* BhRow = (const uint4*)(Bh + (size_t)(j0 + ai) * 128);
    const uint4* BlRow = (const uint4*)(Bl + (size_t)(j0 + ai) * 128);

#pragma unroll
    for (int ch = 0; ch < 2; ch++) {
        // ---- fill smem for this K-chunk (k in [64*ch, 64*ch+64)) ----
#pragma unroll
        for (int q = 0; q < 8; q++) {                 // A: 8 float4 per thread
            int f4 = ch * 16 + half * 8 + q;          // float4 index in full row
            float4 v = aok ? Arow[f4] : make_float4(0.f, 0.f, 0.f, 0.f);
            int k = half * 32 + q * 4;                // col within chunk
            unsigned h01, l01, h23, l23;
            split2(v.x, v.y, h01, l01);
            split2(v.z, v.w, h23, l23);
            unsigned* pH = (unsigned*)(sAh + ai * SAW2 + k);
            unsigned* pL = (unsigned*)(sAl + ai * SAW2 + k);
            pH[0] = h01; pH[1] = h23;
            pL[0] = l01; pL[1] = l23;
        }
#pragma unroll
        for (int q = 0; q < 4; q++) {                 // B: 4 uint4 per plane per thread
            int cglob = ch * 8 + half * 4 + q;        // 16B-chunk index in full row (16 total)
            int cloc = half * 4 + q;                  // chunk within this K-chunk (8 total)
            uint4 vh = BhRow[cglob];
            uint4 vl = BlRow[cglob];
            *(uint4*)(sBh + ai * SAW2 + cloc * 8) = vh;
            *(uint4*)(sBl + ai * SAW2 + cloc * 8) = vl;
        }
        __syncthreads();

        // ---- compute: 4 k16 steps over this chunk ----
#pragma unroll
        for (int ks = 0; ks < 4; ks++) {
            unsigned bh[2][4], bl[2][4];
#pragma unroll
            for (int np = 0; np < 2; np++) {
                uint32_t off = ((wn * 32 + np * 16 + (lane & 15)) * SAW2 +
                                ks * 16 + (lane >> 4) * 8) * 2;
                ldm4(bh[np], sbase + oBh + off);
                ldm4(bl[np], sbase + oBl + off);
            }
#pragma unroll
            for (int mt = 0; mt < 4; mt++) {
                unsigned a_h[4], a_l[4];
                uint32_t off = ((wm * 64 + mt * 16 + (lane & 15)) * SAW2 +
                                ks * 16 + (lane >> 4) * 8) * 2;
                ldm4(a_h, sbase + oAh + off);
                ldm4(a_l, sbase + oAl + off);
#pragma unroll
                for (int nt = 0; nt < 4; nt++) {
                    int np = nt >> 1, od = nt & 1;
                    float* c = acc[mt][nt];
                    mma16816(c, a_h, bh[np][od], bh[np][2 + od]);
                    mma16816(c, a_h, bl[np][od], bl[np][2 + od]);
                    mma16816(c, a_l, bh[np][od], bh[np][2 + od]);
                }
            }
        }
        __syncthreads();
    }

    // ---- epilogue store ----
#pragma unroll
    for (int mt = 0; mt < 4; mt++) {
        int r0 = m0 + wm * 64 + mt * 16 + (lane >> 2);
#pragma unroll
        for (int nt = 0; nt < 4; nt++) {
            int col = j0 + wn * 32 + nt * 8 + (lane & 3) * 2;
            if (r0 < M)
                *(float2*)(C + (size_t)r0 * ldc + col) =
                    make_float2(acc[mt][nt][0], acc[mt][nt][1]);
            if (r0 + 8 < M)
                *(float2*)(C + (size_t)(r0 + 8) * ldc + col) =
                    make_float2(acc[mt][nt][2], acc[mt][nt][3]);
        }
    }
}

// ---------------- scatter-add: agg[dst] += h[src], warp per edge ----------------
__global__ void scatter_kernel() {
    int gw = (blockIdx.x * 256 + threadIdx.x) >> 5;
    int lane = threadIdx.x & 31;
    if (gw >= EEDGES) return;
    int s = g_src[gw], d = g_dst[gw];
    float4 v = *(const float4*)(g_h + (size_t)s * HH + lane * 4);
    float* p = g_agg + (size_t)d * HH + lane * 4;
    asm volatile("red.global.add.v4.f32 [%0], {%1, %2, %3, %4};"
                 :: "l"(p), "f"(v.x), "f"(v.y), "f"(v.z), "f"(v.w) : "memory");
}

// ---------------- GRU elementwise: h = GRU(gi, gh, h) ----------------
__global__ void gru_kernel(const float* __restrict__ b_ih, const float* __restrict__ b_hh) {
    int t = blockIdx.x * 256 + threadIdx.x;   // exactly N*32 threads
    int n = t >> 5;
    int j = (t & 31) * 4;
    size_t gio = (size_t)n * H3 + j;
    float4 ir = *(const float4*)(g_gi + gio);
    float4 iz = *(const float4*)(g_gi + gio + 128);
    float4 in_ = *(const float4*)(g_gi + gio + 256);
    float4 hr = *(const float4*)(g_gh + gio);
    float4 hz = *(const float4*)(g_gh + gio + 128);
    float4 hn = *(const float4*)(g_gh + gio + 256);
    float4 bir = __ldg((const float4*)(b_ih + j));
    float4 biz = __ldg((const float4*)(b_ih + 128 + j));
    float4 bin = __ldg((const float4*)(b_ih + 256 + j));
    float4 bhr = __ldg((const float4*)(b_hh + j));
    float4 bhz = __ldg((const float4*)(b_hh + 128 + j));
    float4 bhn = __ldg((const float4*)(b_hh + 256 + j));
    float4 hv = *(const float4*)(g_h + (size_t)n * HH + j);

    float4 out;
#define GRU1(c)                                                            \
    {                                                                      \
        float r = sigf(ir.c + bir.c + hr.c + bhr.c);                       \
        float z = sigf(iz.c + biz.c + hz.c + bhz.c);                       \
        float ng = tanhfast(in_.c + bin.c + r * (hn.c + bhn.c));           \
        out.c = (1.f - z) * ng + z * hv.c;                                 \
    }
    GRU1(x) GRU1(y) GRU1(z) GRU1(w)
#undef GRU1
    *(float4*)(g_h + (size_t)n * HH + j) = out;
}

// ---------------- head + per-graph sums ----------------
__global__ void lin_kernel(const float* __restrict__ lw, const float* __restrict__ lb,
                           float* __restrict__ out_unc) {
    int gw = (blockIdx.x * 256 + threadIdx.x) >> 5;
    int lane = threadIdx.x & 31;
    float4 a = *(const float4*)(g_h + (size_t)gw * HH + lane * 4);
    a.x = fmaxf(a.x, 0.f); a.y = fmaxf(a.y, 0.f);
    a.z = fmaxf(a.z, 0.f); a.w = fmaxf(a.w, 0.f);
    float4 w = __ldg((const float4*)lw + lane);
    float s = a.x * w.x + a.y * w.y + a.z * w.z + a.w * w.w;
#pragma unroll
    for (int o = 16; o; o >>= 1) s += __shfl_xor_sync(0xffffffffu, s, o);
    if (lane == 0) {
        float v = s + __ldg(lb);
        g_outv[gw] = v;
        out_unc[gw] = v;
        int b = g_batch[gw];
        atomicAdd(&g_gsum[b], v);
        atomicAdd(&g_gcnt[b], 1.f);
    }
}

__global__ void correct_kernel(float* __restrict__ out_corr) {
    int n = blockIdx.x * 256 + threadIdx.x;
    if (n >= NNODES) return;
    int b = g_batch[n];
    out_corr[n] = g_outv[n] - g_gsum[b] / fmaxf(g_gcnt[b], 1.f);
}

// ---------------- launcher ----------------
extern "C" void kernel_launch(void* const* d_in, const int* in_sizes, int n_in,
                              void* d_out, int out_size) {
    const float* x = (const float*)d_in[0];
    const void* edge = d_in[1];
    const void* batch = d_in[2];
    int wi = 3;
    if (in_sizes[3] == 1) wi = 4;   // skip num_graphs scalar if present
    const float* W0     = (const float*)d_in[wi + 0];
    const float* conv_w = (const float*)d_in[wi + 1];
    const float* w_ih   = (const float*)d_in[wi + 2];
    const float* b_ih   = (const float*)d_in[wi + 3];
    const float* w_hh   = (const float*)d_in[wi + 4];
    const float* b_hh   = (const float*)d_in[wi + 5];
    const float* lin1_w = (const float*)d_in[wi + 6];
    const float* lin1_b = (const float*)d_in[wi + 7];

    float* out = (float*)d_out;
    float* out_corr = out;
    float* out_emb  = out + NNODES;
    float* out_unc  = out + NNODES + (size_t)NNODES * HH;

    cudaFuncSetAttribute(mma_gemm_kernel, cudaFuncAttributeMaxDynamicSharedMemorySize,
                         MMA_SMEM);

    float *p_h, *p_m, *p_agg, *p_gi, *p_gh;
    cudaGetSymbolAddress((void**)&p_h, g_h);
    cudaGetSymbolAddress((void**)&p_m, g_m);
    cudaGetSymbolAddress((void**)&p_agg, g_agg);
    cudaGetSymbolAddress((void**)&p_gi, g_gi);
    cudaGetSymbolAddress((void**)&p_gh, g_gh);
    unsigned short *p_cwh, *p_cwl, *p_ihh, *p_ihl, *p_hhh, *p_hhl;
    cudaGetSymbolAddress((void**)&p_cwh, g_cw_h);
    cudaGetSymbolAddress((void**)&p_cwl, g_cw_l);
    cudaGetSymbolAddress((void**)&p_ihh, g_ih_h);
    cudaGetSymbolAddress((void**)&p_ihl, g_ih_l);
    cudaGetSymbolAddress((void**)&p_hhh, g_hh_h);
    cudaGetSymbolAddress((void**)&p_hhl, g_hh_l);

    zero_small_kernel<<<1, 128>>>();
    detect_kernel<<<256, 256>>>((const unsigned int*)edge, 2LL * EEDGES, 0);
    detect_kernel<<<256, 256>>>((const unsigned int*)batch, (long long)NNODES, 1);
    convert_edges_kernel<<<(EEDGES + 255) / 256, 256>>>(edge);
    convert_batch_kernel<<<(NNODES + 255) / 256, 256>>>(batch);
    conv_w_split_kernel<<<(LLAYERS * HH * HH + 255) / 256, 256>>>(conv_w);
    w2_split_kernel<<<(H3 * HH + 255) / 256, 256>>>(w_ih, w_hh);

    const int MT = (NNODES + 127) / 128;   // 782
    embed_kernel<<<MT, 256>>>(x, W0, out_emb);

    for (int l = 0; l < LLAYERS; l++) {
        // scatter(h) then one GEMM (linearity: sum(h[src]) @ W == sum(h[src] @ W))
        zero_agg_kernel<<<NNODES * HH / (256 * 4), 256>>>();
        scatter_kernel<<<EEDGES * 32 / 256, 256>>>();
        mma_gemm_kernel<<<dim3(MT, 1), 256, MMA_SMEM>>>(
            p_agg, p_cwh + (size_t)l * HH * HH, p_cwl + (size_t)l * HH * HH,
            p_m, NNODES, HH);
        mma_gemm_kernel<<<dim3(MT, 3), 256, MMA_SMEM>>>(p_m, p_ihh, p_ihl, p_gi, NNODES, H3);
        mma_gemm_kernel<<<dim3(MT, 3), 256, MMA_SMEM>>>(p_h, p_hhh, p_hhl, p_gh, NNODES, H3);
        gru_kernel<<<NNODES * 32 / 256, 256>>>(b_ih, b_hh);
    }

    lin_kernel<<<NNODES * 32 / 256, 256>>>(lin1_w, lin1_b, out_unc);
    correct_kernel<<<(NNODES + 255) / 256, 256>>>(out_corr);
}